// round 1
// baseline (speedup 1.0000x reference)
#include <cuda_runtime.h>
#include <cuda_bf16.h>
#include <math.h>

// ---------------------------------------------------------------------------
// DVDMixer: B = 32*128 = 4096 rows
// N_AGENTS=16, RNN_H=64, N_HEADS=4, GAT_D=32, EMB=32, SDIM=128
// ---------------------------------------------------------------------------

#define BROWS 4096

// g[b][h][n][d] : 4096 * 4 * 16 * 32 floats = 33.5 MB scratch
__device__ float g_buf[(size_t)BROWS * 4 * 16 * 32];

// ============================= Kernel A: GAT ================================
// 8 rows per block, 256 threads, 512 blocks.
// smem floats: W(8192) hs(8192) hp(16384) att(256) src(512) dst(512) = 34048
#define SMEM_A_FLOATS 34048

__global__ __launch_bounds__(256, 1)
void gat_kernel(const float* __restrict__ hs_g,
                const float* __restrict__ Wg,
                const float* __restrict__ att)
{
    extern __shared__ float sm[];
    float* sW   = sm;            // [64][128]
    float* shs  = sW  + 8192;    // [8][16][64]
    float* shp  = shs + 8192;    // [8][16][128]
    float* satt = shp + 16384;   // [4][64]
    float* ssrc = satt + 256;    // [8][4][16]
    float* sdst = ssrc + 512;    // [8][4][16]

    const int tid  = threadIdx.x;
    const int brow = blockIdx.x * 8;

    // cooperative loads (all coalesced float4)
    for (int i = tid; i < 2048; i += 256)
        ((float4*)sW)[i] = ((const float4*)Wg)[i];
    const float4* hsg4 = (const float4*)(hs_g + (size_t)brow * 1024);
    for (int i = tid; i < 2048; i += 256)
        ((float4*)shs)[i] = hsg4[i];
    if (tid < 64) ((float4*)satt)[tid] = ((const float4*)att)[tid];
    __syncthreads();

    // hp[r][n][c] = sum_k hs[r][n][k] * W[k][c]   (warp r, lane handles 4 cols)
    {
        const int r = tid >> 5, lane = tid & 31;
        const int c0 = lane * 4;
        for (int n = 0; n < 16; n++) {
            float4 acc = make_float4(0.f, 0.f, 0.f, 0.f);
            const float* hrow = shs + (r * 16 + n) * 64;
            #pragma unroll 16
            for (int k = 0; k < 64; k++) {
                float hv = hrow[k];
                float4 w = *(const float4*)(sW + k * 128 + c0);
                acc.x += hv * w.x; acc.y += hv * w.y;
                acc.z += hv * w.z; acc.w += hv * w.w;
            }
            *(float4*)(shp + (r * 16 + n) * 128 + c0) = acc;
        }
    }
    __syncthreads();

    // src/dst[r][h][n]
    if (tid < 128) {
        const int r = tid >> 4, n = tid & 15;
        for (int h = 0; h < 4; h++) {
            float s_ = 0.f, d_ = 0.f;
            const float* hp = shp + (r * 16 + n) * 128 + h * 32;
            const float* as = satt + h * 64;
            #pragma unroll
            for (int d = 0; d < 32; d++) {
                s_ += hp[d] * as[d];
                d_ += hp[d] * as[32 + d];
            }
            ssrc[(r * 4 + h) * 16 + n] = s_;
            sdst[(r * 4 + h) * 16 + n] = d_;
        }
    }
    __syncthreads();

    // attention softmax + g = elu(attn @ hp)
    for (int it = 0; it < 2; it++) {
        const int idx = tid + it * 256;           // 0..511 = (r,h,i)
        const int r = idx >> 6;
        const int h = (idx >> 4) & 3;
        const int i = idx & 15;
        const float sv = ssrc[(r * 4 + h) * 16 + i];
        float p[16];
        float m = -1e30f;
        #pragma unroll
        for (int j = 0; j < 16; j++) {
            float e = sv + sdst[(r * 4 + h) * 16 + j];
            e = e > 0.f ? e : 0.2f * e;           // leaky_relu 0.2
            p[j] = e;
            m = fmaxf(m, e);
        }
        float sum = 0.f;
        #pragma unroll
        for (int j = 0; j < 16; j++) { p[j] = expf(p[j] - m); sum += p[j]; }
        const float inv = 1.f / sum;

        float* gout = g_buf + (((size_t)(brow + r) * 4 + h) * 16 + i) * 32;
        #pragma unroll
        for (int d0 = 0; d0 < 32; d0 += 4) {
            float4 a = make_float4(0.f, 0.f, 0.f, 0.f);
            #pragma unroll
            for (int j = 0; j < 16; j++) {
                const float pj = p[j];
                const float* hp = shp + (r * 16 + j) * 128 + h * 32 + d0;
                a.x += pj * hp[0]; a.y += pj * hp[1];
                a.z += pj * hp[2]; a.w += pj * hp[3];
            }
            a.x *= inv; a.y *= inv; a.z *= inv; a.w *= inv;
            a.x = a.x > 0.f ? a.x : expm1f(a.x);  // elu
            a.y = a.y > 0.f ? a.y : expm1f(a.y);
            a.z = a.z > 0.f ? a.z : expm1f(a.z);
            a.w = a.w > 0.f ? a.w : expm1f(a.w);
            *(float4*)(gout + d0) = a;
        }
    }
}

// =========================== Kernel B: fused mixer ==========================
// 16 rows per block, 256 blocks, 256 threads.
// smem floats: sT(129*16=2064) qs(256) Wc(8*1024=8192) ws(16*1032=16512)
//              gsm(256*36=9216) w1acc(256*33=8448)  = 44688 floats = 178752 B
#define SMEM_B_FLOATS 44688

__global__ __launch_bounds__(256, 1)
void mix_kernel(const float* __restrict__ qs_g,
                const float* __restrict__ s_g,
                const float* __restrict__ unc_g,
                const float* __restrict__ w1sW,
                const float* __restrict__ w1sb,
                const float* __restrict__ b1W,
                const float* __restrict__ b1b,
                const float* __restrict__ wfW,
                const float* __restrict__ wfb,
                const float* __restrict__ V1W,
                const float* __restrict__ V1b,
                const float* __restrict__ V2W,
                const float* __restrict__ V2b,
                float* __restrict__ out)
{
    extern __shared__ float sm[];
    float* sT    = sm;               // [129][16]  s_aug transposed
    float* sqs   = sT + 2064;        // [16][16]
    float* Wc    = sqs + 256;        // [8][1024]  K-chunk of w1s_W
    float* ws    = Wc + 8192;        // [16][1032] w1_state tile (padded)
    float* gsm   = ws + 16512;       // [256][36]  g tile (padded d-stride)
    float* w1acc = gsm + 9216;       // [256][33]  sum_h |w1_heads| (padded)

    const int tid  = threadIdx.x;
    const int brow = blockIdx.x * 16;

    // stage s (transposed), unc, qs
    for (int idx = tid; idx < 2048; idx += 256) {
        int r = idx >> 7, k = idx & 127;
        sT[k * 16 + r] = s_g[(size_t)(brow + r) * 128 + k];
    }
    if (tid < 16) sT[128 * 16 + tid] = unc_g[brow + tid];
    if (tid < 256) {
        int r = tid >> 4, n = tid & 15;
        sqs[tid] = qs_g[(size_t)(brow + r) * 16 + n];
    }
    for (int idx = tid; idx < 8448; idx += 256) w1acc[idx] = 0.f;
    __syncthreads();

    const int colg = tid & 127;   // 128 column-groups of 8
    const int rowg = tid >> 7;    // 2 row-groups of 8
    const int c0 = colg * 8;
    const int r0 = rowg * 8;

    for (int h = 0; h < 4; h++) {
        // ---- GEMM: ws[16][1024] = s_aug[16][129] @ w1s_W[129][head h cols]
        float acc[8][8];
        #pragma unroll
        for (int i = 0; i < 8; i++)
            #pragma unroll
            for (int j = 0; j < 8; j++) acc[i][j] = 0.f;

        for (int kb = 0; kb < 129; kb += 8) {
            const int kt = (129 - kb) < 8 ? (129 - kb) : 8;
            const int tot4 = kt * 256;           // float4 count
            for (int i4 = tid; i4 < tot4; i4 += 256) {
                int kk = i4 >> 8, cq = i4 & 255;
                ((float4*)(Wc + kk * 1024))[cq] =
                    ((const float4*)(w1sW + (size_t)(kb + kk) * 4096 + h * 1024))[cq];
            }
            __syncthreads();
            #pragma unroll
            for (int kk = 0; kk < 8; kk++) {
                if (kk >= kt) break;
                float4 sa = *(const float4*)(sT + (kb + kk) * 16 + r0);
                float4 sb = *(const float4*)(sT + (kb + kk) * 16 + r0 + 4);
                float4 w0 = *(const float4*)(Wc + kk * 1024 + c0);
                float4 w1 = *(const float4*)(Wc + kk * 1024 + c0 + 4);
                float sr[8] = {sa.x, sa.y, sa.z, sa.w, sb.x, sb.y, sb.z, sb.w};
                float wc[8] = {w0.x, w0.y, w0.z, w0.w, w1.x, w1.y, w1.z, w1.w};
                #pragma unroll
                for (int i = 0; i < 8; i++)
                    #pragma unroll
                    for (int j = 0; j < 8; j++)
                        acc[i][j] += sr[i] * wc[j];
            }
            __syncthreads();
        }

        // bias + write w1_state tile to padded smem
        {
            float4 bb0 = __ldg((const float4*)(w1sb + h * 1024 + c0));
            float4 bb1 = __ldg((const float4*)(w1sb + h * 1024 + c0 + 4));
            float bj[8] = {bb0.x, bb0.y, bb0.z, bb0.w, bb1.x, bb1.y, bb1.z, bb1.w};
            #pragma unroll
            for (int i = 0; i < 8; i++)
                #pragma unroll
                for (int j = 0; j < 8; j++)
                    ws[(r0 + i) * 1032 + c0 + j] = acc[i][j] + bj[j];
        }

        // load g tile for this head (float4, padded stride 36)
        for (int i4 = tid; i4 < 2048; i4 += 256) {
            int rn = i4 >> 3, dq = i4 & 7;
            *(float4*)(gsm + rn * 36 + dq * 4) =
                *(const float4*)(g_buf + ((size_t)(brow + (rn >> 4)) * 4 + h) * 512
                                 + (rn & 15) * 32 + dq * 4);
        }
        __syncthreads();

        // contraction: w1acc[r][n][e] += | sum_d ws[r][e*32+d] * g[r][n][d] |
        {
            const int r = tid >> 4, n = tid & 15;
            float greg[32];
            #pragma unroll
            for (int q = 0; q < 8; q++) {
                float4 gv = *(const float4*)(gsm + (r * 16 + n) * 36 + q * 4);
                greg[q * 4 + 0] = gv.x; greg[q * 4 + 1] = gv.y;
                greg[q * 4 + 2] = gv.z; greg[q * 4 + 3] = gv.w;
            }
            const float* wrow = ws + r * 1032;
            float* wa = w1acc + (r * 16 + n) * 33;
            #pragma unroll
            for (int e = 0; e < 32; e++) {
                const float* wp = wrow + e * 32;
                float a = 0.f;
                #pragma unroll
                for (int q = 0; q < 8; q++) {
                    float4 wv = *(const float4*)(wp + q * 4);
                    a += wv.x * greg[q * 4 + 0];
                    a += wv.y * greg[q * 4 + 1];
                    a += wv.z * greg[q * 4 + 2];
                    a += wv.w * greg[q * 4 + 3];
                }
                wa[e] += fabsf(a);
            }
        }
        __syncthreads();
    }

    // ------------------------------ epilogue --------------------------------
    {
        const int r = tid >> 4, j = tid & 15;
        float b1v[2], wfv[2];
        float vpart = 0.f;
        #pragma unroll
        for (int t = 0; t < 2; t++) {
            const int e = j + 16 * t;
            float ab = 0.f, aw = 0.f, av = 0.f;
            for (int k = 0; k < 128; k++) {
                const float sv = sT[k * 16 + r];
                ab += sv * __ldg(b1W + k * 32 + e);
                aw += sv * __ldg(wfW + k * 32 + e);
                av += sv * __ldg(V1W + k * 32 + e);
            }
            b1v[t] = ab + __ldg(b1b + e);
            wfv[t] = fabsf(aw + __ldg(wfb + e));
            float v1 = fmaxf(av + __ldg(V1b + e), 0.f);
            vpart += v1 * __ldg(V2W + e);
        }
        #pragma unroll
        for (int d = 8; d; d >>= 1)
            vpart += __shfl_down_sync(0xffffffffu, vpart, d, 16);

        float ysum = 0.f;
        #pragma unroll
        for (int t = 0; t < 2; t++) {
            const int e = j + 16 * t;
            float ha = 0.f;
            #pragma unroll
            for (int n = 0; n < 16; n++)
                ha += sqs[r * 16 + n] * w1acc[(r * 16 + n) * 33 + e];
            float hid = 0.25f * ha + b1v[t];
            hid = hid > 0.f ? hid : expm1f(hid);   // elu
            ysum += hid * wfv[t];
        }
        #pragma unroll
        for (int d = 8; d; d >>= 1)
            ysum += __shfl_down_sync(0xffffffffu, ysum, d, 16);

        if (j == 0)
            out[brow + r] = ysum + vpart + __ldg(V2b);
    }
}

// =============================================================================
extern "C" void kernel_launch(void* const* d_in, const int* in_sizes, int n_in,
                              void* d_out, int out_size)
{
    const float* qs   = (const float*)d_in[0];   // agent_qs   (32,128,16)
    const float* st   = (const float*)d_in[1];   // states     (32,128,128)
    const float* hs   = (const float*)d_in[2];   // hidden     (32,128,16,64)
    const float* unc  = (const float*)d_in[3];   // uncertainty(32,128,1)
    const float* Wg   = (const float*)d_in[4];   // W_gat      (64,128)
    const float* att  = (const float*)d_in[5];   // att_a      (1,4,64)
    const float* w1sW = (const float*)d_in[6];   // (129,4096)
    const float* w1sb = (const float*)d_in[7];   // (4096,)
    const float* b1W  = (const float*)d_in[8];   // (128,32)
    const float* b1b  = (const float*)d_in[9];
    const float* wfW  = (const float*)d_in[10];  // (128,32)
    const float* wfb  = (const float*)d_in[11];
    const float* V1W  = (const float*)d_in[12];  // (128,32)
    const float* V1b  = (const float*)d_in[13];
    const float* V2W  = (const float*)d_in[14];  // (32,1)
    const float* V2b  = (const float*)d_in[15];
    float* out = (float*)d_out;

    (void)in_sizes; (void)n_in; (void)out_size;

    cudaFuncSetAttribute(gat_kernel, cudaFuncAttributeMaxDynamicSharedMemorySize,
                         SMEM_A_FLOATS * sizeof(float));
    cudaFuncSetAttribute(mix_kernel, cudaFuncAttributeMaxDynamicSharedMemorySize,
                         SMEM_B_FLOATS * sizeof(float));

    gat_kernel<<<512, 256, SMEM_A_FLOATS * sizeof(float)>>>(hs, Wg, att);
    mix_kernel<<<256, 256, SMEM_B_FLOATS * sizeof(float)>>>(
        qs, st, unc, w1sW, w1sb, b1W, b1b, wfW, wfb, V1W, V1b, V2W, V2b, out);
}

// round 2
// speedup vs baseline: 1.4311x; 1.4311x over previous
#include <cuda_runtime.h>
#include <cuda_bf16.h>
#include <math.h>

// ---------------------------------------------------------------------------
// DVDMixer: B = 32*128 = 4096 rows
// N_AGENTS=16, RNN_H=64, N_HEADS=4, GAT_D=32, EMB=32, SDIM=128
// ---------------------------------------------------------------------------

#define BROWS 4096

// g[b][h][n][d] : 4096 * 4 * 16 * 32 floats = 33.5 MB scratch
__device__ float g_buf[(size_t)BROWS * 4 * 16 * 32];

// ============================= Kernel A: GAT ================================
#define SMEM_A_FLOATS 34048

__global__ __launch_bounds__(256, 1)
void gat_kernel(const float* __restrict__ hs_g,
                const float* __restrict__ Wg,
                const float* __restrict__ att)
{
    extern __shared__ float sm[];
    float* sW   = sm;            // [64][128]
    float* shs  = sW  + 8192;    // [8][16][64]
    float* shp  = shs + 8192;    // [8][16][128]
    float* satt = shp + 16384;   // [4][64]
    float* ssrc = satt + 256;    // [8][4][16]
    float* sdst = ssrc + 512;    // [8][4][16]

    const int tid  = threadIdx.x;
    const int brow = blockIdx.x * 8;

    for (int i = tid; i < 2048; i += 256)
        ((float4*)sW)[i] = ((const float4*)Wg)[i];
    const float4* hsg4 = (const float4*)(hs_g + (size_t)brow * 1024);
    for (int i = tid; i < 2048; i += 256)
        ((float4*)shs)[i] = hsg4[i];
    if (tid < 64) ((float4*)satt)[tid] = ((const float4*)att)[tid];
    __syncthreads();

    {
        const int r = tid >> 5, lane = tid & 31;
        const int c0 = lane * 4;
        for (int n = 0; n < 16; n++) {
            float4 acc = make_float4(0.f, 0.f, 0.f, 0.f);
            const float* hrow = shs + (r * 16 + n) * 64;
            #pragma unroll 16
            for (int k = 0; k < 64; k++) {
                float hv = hrow[k];
                float4 w = *(const float4*)(sW + k * 128 + c0);
                acc.x += hv * w.x; acc.y += hv * w.y;
                acc.z += hv * w.z; acc.w += hv * w.w;
            }
            *(float4*)(shp + (r * 16 + n) * 128 + c0) = acc;
        }
    }
    __syncthreads();

    if (tid < 128) {
        const int r = tid >> 4, n = tid & 15;
        for (int h = 0; h < 4; h++) {
            float s_ = 0.f, d_ = 0.f;
            const float* hp = shp + (r * 16 + n) * 128 + h * 32;
            const float* as = satt + h * 64;
            #pragma unroll
            for (int d = 0; d < 32; d++) {
                s_ += hp[d] * as[d];
                d_ += hp[d] * as[32 + d];
            }
            ssrc[(r * 4 + h) * 16 + n] = s_;
            sdst[(r * 4 + h) * 16 + n] = d_;
        }
    }
    __syncthreads();

    for (int it = 0; it < 2; it++) {
        const int idx = tid + it * 256;
        const int r = idx >> 6;
        const int h = (idx >> 4) & 3;
        const int i = idx & 15;
        const float sv = ssrc[(r * 4 + h) * 16 + i];
        float p[16];
        float m = -1e30f;
        #pragma unroll
        for (int j = 0; j < 16; j++) {
            float e = sv + sdst[(r * 4 + h) * 16 + j];
            e = e > 0.f ? e : 0.2f * e;
            p[j] = e;
            m = fmaxf(m, e);
        }
        float sum = 0.f;
        #pragma unroll
        for (int j = 0; j < 16; j++) { p[j] = expf(p[j] - m); sum += p[j]; }
        const float inv = 1.f / sum;

        float* gout = g_buf + (((size_t)(brow + r) * 4 + h) * 16 + i) * 32;
        #pragma unroll
        for (int d0 = 0; d0 < 32; d0 += 4) {
            float4 a = make_float4(0.f, 0.f, 0.f, 0.f);
            #pragma unroll
            for (int j = 0; j < 16; j++) {
                const float pj = p[j];
                const float* hp = shp + (r * 16 + j) * 128 + h * 32 + d0;
                a.x += pj * hp[0]; a.y += pj * hp[1];
                a.z += pj * hp[2]; a.w += pj * hp[3];
            }
            a.x *= inv; a.y *= inv; a.z *= inv; a.w *= inv;
            a.x = a.x > 0.f ? a.x : expm1f(a.x);
            a.y = a.y > 0.f ? a.y : expm1f(a.y);
            a.z = a.z > 0.f ? a.z : expm1f(a.z);
            a.w = a.w > 0.f ? a.w : expm1f(a.w);
            *(float4*)(gout + d0) = a;
        }
    }
}

// =========================== Kernel B: fused mixer v2 =======================
// 16 rows/block, 256 blocks, 256 threads, 2 CTAs/SM.
// smem floats: sT(2064) sqs(256) Wc(2*8*1024=16384) w1acc(256*33=8448)
//            = 27152 floats = 108608 bytes  -> 2 CTAs/SM (217 KB)
#define SMEM_B_FLOATS (2064 + 256 + 16384 + 8448)

__device__ __forceinline__ void cp_async16(float* s, const float* g) {
    unsigned a = (unsigned)__cvta_generic_to_shared(s);
    asm volatile("cp.async.cg.shared.global [%0], [%1], 16;" :: "r"(a), "l"(g));
}

__global__ __launch_bounds__(256, 2)
void mix_kernel(const float* __restrict__ qs_g,
                const float* __restrict__ s_g,
                const float* __restrict__ unc_g,
                const float* __restrict__ w1sW,
                const float* __restrict__ w1sb,
                const float* __restrict__ b1W,
                const float* __restrict__ b1b,
                const float* __restrict__ wfW,
                const float* __restrict__ wfb,
                const float* __restrict__ V1W,
                const float* __restrict__ V1b,
                const float* __restrict__ V2W,
                const float* __restrict__ V2b,
                float* __restrict__ out)
{
    extern __shared__ float sm[];
    float* sT    = sm;               // [129][16]  s_aug transposed
    float* sqs   = sT + 2064;        // [16][16]
    float* Wc    = sqs + 256;        // 2 x [8][1024] double-buffered chunk
    float* w1acc = Wc + 16384;       // [256][33]  sum_h |w1_heads| (padded)

    const int tid  = threadIdx.x;
    const int brow = blockIdx.x * 16;
    const int lane = tid & 31;

    // stage s (transposed), unc, qs; zero w1acc
    for (int idx = tid; idx < 2048; idx += 256) {
        int r = idx >> 7, k = idx & 127;
        sT[k * 16 + r] = s_g[(size_t)(brow + r) * 128 + k];
    }
    if (tid < 16) sT[128 * 16 + tid] = unc_g[brow + tid];
    {
        int r = tid >> 4, n = tid & 15;
        sqs[tid] = qs_g[(size_t)(brow + r) * 16 + n];
    }
    for (int idx = tid; idx < 8448; idx += 256) w1acc[idx] = 0.f;
    __syncthreads();

    const int colg = tid & 127;      // 128 column-groups
    const int rowg = tid >> 7;       // 2 row-groups of 8
    const int cA   = colg * 4;       // first 4-col group; second at 512+cA
    const int r0   = rowg * 8;
    // contraction indices: e0 = colg/8, d0 = (colg%8)*4
    const int e0 = colg >> 3;
    const int d0 = (colg & 7) * 4;

    float* Wb[2] = { Wc, Wc + 8192 };

    for (int h = 0; h < 4; h++) {
        // prefetch this head's g tile into L2 (one 128B line per thread)
        {
            const float* gp = g_buf +
                (((size_t)(brow + (tid >> 4)) * 4 + h) * 16 + (tid & 15)) * 32;
            asm volatile("prefetch.global.L2 [%0];" :: "l"(gp));
        }

        float acc[8][8];
        #pragma unroll
        for (int i = 0; i < 8; i++)
            #pragma unroll
            for (int j = 0; j < 8; j++) acc[i][j] = 0.f;

        // prologue: chunk 0 -> buf 0  (8 rows x 1024 cols, 8 cp.async/thread)
        #pragma unroll
        for (int q = 0; q < 8; q++) {
            int i4 = tid + q * 256;
            int kk = i4 >> 8, c = (i4 & 255) * 4;
            cp_async16(Wb[0] + kk * 1024 + c,
                       w1sW + (size_t)kk * 4096 + h * 1024 + c);
        }
        asm volatile("cp.async.commit_group;");

        for (int kb = 0; kb < 16; kb++) {
            if (kb < 15) {
                float* dst = Wb[(kb + 1) & 1];
                const float* src = w1sW + (size_t)(kb + 1) * 8 * 4096 + h * 1024;
                #pragma unroll
                for (int q = 0; q < 8; q++) {
                    int i4 = tid + q * 256;
                    int kk = i4 >> 8, c = (i4 & 255) * 4;
                    cp_async16(dst + kk * 1024 + c, src + (size_t)kk * 4096 + c);
                }
                asm volatile("cp.async.commit_group;");
                asm volatile("cp.async.wait_group 1;");
            } else {
                asm volatile("cp.async.wait_group 0;");
            }
            __syncthreads();

            const float* W = Wb[kb & 1];
            const float* sTk = sT + kb * 8 * 16;
            #pragma unroll
            for (int kk = 0; kk < 8; kk++) {
                float4 sa = *(const float4*)(sTk + kk * 16 + r0);
                float4 sb = *(const float4*)(sTk + kk * 16 + r0 + 4);
                float4 w0 = *(const float4*)(W + kk * 1024 + cA);
                float4 w1 = *(const float4*)(W + kk * 1024 + 512 + cA);
                float sr[8] = {sa.x, sa.y, sa.z, sa.w, sb.x, sb.y, sb.z, sb.w};
                #pragma unroll
                for (int i = 0; i < 8; i++) {
                    acc[i][0] += sr[i] * w0.x; acc[i][1] += sr[i] * w0.y;
                    acc[i][2] += sr[i] * w0.z; acc[i][3] += sr[i] * w0.w;
                    acc[i][4] += sr[i] * w1.x; acc[i][5] += sr[i] * w1.y;
                    acc[i][6] += sr[i] * w1.z; acc[i][7] += sr[i] * w1.w;
                }
            }
            __syncthreads();
        }

        // tail: K row 128 (uncertainty column) as rank-1 update, + bias
        {
            float4 w0 = __ldg((const float4*)(w1sW + (size_t)128 * 4096 + h * 1024 + cA));
            float4 w1 = __ldg((const float4*)(w1sW + (size_t)128 * 4096 + h * 1024 + 512 + cA));
            float4 b0 = __ldg((const float4*)(w1sb + h * 1024 + cA));
            float4 b1 = __ldg((const float4*)(w1sb + h * 1024 + 512 + cA));
            #pragma unroll
            for (int i = 0; i < 8; i++) {
                float su = sT[128 * 16 + r0 + i];
                acc[i][0] += su * w0.x + 0.f; acc[i][1] += su * w0.y;
                acc[i][2] += su * w0.z;       acc[i][3] += su * w0.w;
                acc[i][4] += su * w1.x;       acc[i][5] += su * w1.y;
                acc[i][6] += su * w1.z;       acc[i][7] += su * w1.w;
                acc[i][0] += b0.x; acc[i][1] += b0.y; acc[i][2] += b0.z; acc[i][3] += b0.w;
                acc[i][4] += b1.x; acc[i][5] += b1.y; acc[i][6] += b1.z; acc[i][7] += b1.w;
            }
        }

        // contraction in registers + shfl reduce over the 8-lane d-octet.
        // thread owns cols e0 (group0) and e0+16 (group1), d segment d0..d0+3,
        // for rows r0..r0+7.
        for (int n = 0; n < 16; n++) {
            #pragma unroll
            for (int i = 0; i < 8; i++) {
                const float4 gv = __ldg((const float4*)(
                    g_buf + (((size_t)(brow + r0 + i) * 4 + h) * 16 + n) * 32 + d0));
                float p0 = acc[i][0] * gv.x + acc[i][1] * gv.y
                         + acc[i][2] * gv.z + acc[i][3] * gv.w;
                float p1 = acc[i][4] * gv.x + acc[i][5] * gv.y
                         + acc[i][6] * gv.z + acc[i][7] * gv.w;
                p0 += __shfl_xor_sync(0xffffffffu, p0, 1);
                p1 += __shfl_xor_sync(0xffffffffu, p1, 1);
                p0 += __shfl_xor_sync(0xffffffffu, p0, 2);
                p1 += __shfl_xor_sync(0xffffffffu, p1, 2);
                p0 += __shfl_xor_sync(0xffffffffu, p0, 4);
                p1 += __shfl_xor_sync(0xffffffffu, p1, 4);
                if ((lane & 7) == 0) {
                    float* wa = w1acc + ((r0 + i) * 16 + n) * 33;
                    wa[e0]      += fabsf(p0);
                    wa[e0 + 16] += fabsf(p1);
                }
            }
        }
        __syncthreads();
    }

    // ------------------------------ epilogue --------------------------------
    {
        const int r = tid >> 4, j = tid & 15;
        float b1v[2], wfv[2];
        float vpart = 0.f;
        #pragma unroll
        for (int t = 0; t < 2; t++) {
            const int e = j + 16 * t;
            float ab = 0.f, aw = 0.f, av = 0.f;
            for (int k = 0; k < 128; k++) {
                const float sv = sT[k * 16 + r];
                ab += sv * __ldg(b1W + k * 32 + e);
                aw += sv * __ldg(wfW + k * 32 + e);
                av += sv * __ldg(V1W + k * 32 + e);
            }
            b1v[t] = ab + __ldg(b1b + e);
            wfv[t] = fabsf(aw + __ldg(wfb + e));
            float v1 = fmaxf(av + __ldg(V1b + e), 0.f);
            vpart += v1 * __ldg(V2W + e);
        }
        #pragma unroll
        for (int d = 8; d; d >>= 1)
            vpart += __shfl_down_sync(0xffffffffu, vpart, d, 16);

        float ysum = 0.f;
        #pragma unroll
        for (int t = 0; t < 2; t++) {
            const int e = j + 16 * t;
            float ha = 0.f;
            #pragma unroll
            for (int n = 0; n < 16; n++)
                ha += sqs[r * 16 + n] * w1acc[(r * 16 + n) * 33 + e];
            float hid = 0.25f * ha + b1v[t];
            hid = hid > 0.f ? hid : expm1f(hid);
            ysum += hid * wfv[t];
        }
        #pragma unroll
        for (int d = 8; d; d >>= 1)
            ysum += __shfl_down_sync(0xffffffffu, ysum, d, 16);

        if (j == 0)
            out[brow + r] = ysum + vpart + __ldg(V2b);
    }
}

// =============================================================================
extern "C" void kernel_launch(void* const* d_in, const int* in_sizes, int n_in,
                              void* d_out, int out_size)
{
    const float* qs   = (const float*)d_in[0];
    const float* st   = (const float*)d_in[1];
    const float* hs   = (const float*)d_in[2];
    const float* unc  = (const float*)d_in[3];
    const float* Wg   = (const float*)d_in[4];
    const float* att  = (const float*)d_in[5];
    const float* w1sW = (const float*)d_in[6];
    const float* w1sb = (const float*)d_in[7];
    const float* b1W  = (const float*)d_in[8];
    const float* b1b  = (const float*)d_in[9];
    const float* wfW  = (const float*)d_in[10];
    const float* wfb  = (const float*)d_in[11];
    const float* V1W  = (const float*)d_in[12];
    const float* V1b  = (const float*)d_in[13];
    const float* V2W  = (const float*)d_in[14];
    const float* V2b  = (const float*)d_in[15];
    float* out = (float*)d_out;

    (void)in_sizes; (void)n_in; (void)out_size;

    cudaFuncSetAttribute(gat_kernel, cudaFuncAttributeMaxDynamicSharedMemorySize,
                         SMEM_A_FLOATS * sizeof(float));
    cudaFuncSetAttribute(mix_kernel, cudaFuncAttributeMaxDynamicSharedMemorySize,
                         SMEM_B_FLOATS * sizeof(float));

    gat_kernel<<<512, 256, SMEM_A_FLOATS * sizeof(float)>>>(hs, Wg, att);
    mix_kernel<<<256, 256, SMEM_B_FLOATS * sizeof(float)>>>(
        qs, st, unc, w1sW, w1sb, b1W, b1b, wfW, wfb, V1W, V1b, V2W, V2b, out);
}

// round 3
// speedup vs baseline: 1.6092x; 1.1244x over previous
#include <cuda_runtime.h>
#include <cuda_bf16.h>
#include <math.h>

// ---------------------------------------------------------------------------
// DVDMixer: B = 32*128 = 4096 rows
// N_AGENTS=16, RNN_H=64, N_HEADS=4, GAT_D=32, EMB=32, SDIM=128
// ---------------------------------------------------------------------------

#define BROWS 4096

// g[b][h][n][d]: 4096*4*16*32 floats = 33.5 MB scratch (fits L2)
__device__ float g_buf[(size_t)BROWS * 4 * 16 * 32];
// epi_buf[row][0:32]=b1v, [32:64]=|wf|, [64]=v (incl V2b)
__device__ float epi_buf[(size_t)BROWS * 65];

// ============================= Kernel A: GAT + epilogue prep ================
// 8 rows/block (1 warp per row), 256 threads, 512 blocks, 3 CTAs/SM.
// smem: shs [8][16][64] = 8192 fl + sattn [8][16][20] = 2560 fl = 43 KB
#define GAT_SMEM_FLOATS (8192 + 2560)

__global__ __launch_bounds__(256, 3)
void gat_kernel(const float* __restrict__ hs_g,
                const float* __restrict__ Wg,
                const float* __restrict__ att,
                const float* __restrict__ s_g,
                const float* __restrict__ b1W, const float* __restrict__ b1b,
                const float* __restrict__ wfW, const float* __restrict__ wfb,
                const float* __restrict__ V1W, const float* __restrict__ V1b,
                const float* __restrict__ V2W, const float* __restrict__ V2b)
{
    extern __shared__ float sm[];
    float* shs   = sm;            // [8][16][64]
    float* sattn = sm + 8192;     // [8][16][20]

    const int tid  = threadIdx.x;
    const int lane = tid & 31;
    const int w    = tid >> 5;     // warp = local row
    const int brow = blockIdx.x * 8;

    // stage hs (coalesced float4)
    const float4* src4 = (const float4*)(hs_g + (size_t)brow * 1024);
    for (int i = tid; i < 2048; i += 256)
        ((float4*)shs)[i] = src4[i];

    // ---- epilogue prep for row (brow+w): lane = e (EMB=32) ----
    {
        const int row = brow + w;
        float ab = 0.f, aw = 0.f, av = 0.f;
        const float* srow = s_g + (size_t)row * 128;
        #pragma unroll 4
        for (int k = 0; k < 128; k++) {
            const float sv = __ldg(srow + k);
            ab += sv * __ldg(b1W + k * 32 + lane);
            aw += sv * __ldg(wfW + k * 32 + lane);
            av += sv * __ldg(V1W + k * 32 + lane);
        }
        const float b1v = ab + __ldg(b1b + lane);
        const float wfv = fabsf(aw + __ldg(wfb + lane));
        float v1 = fmaxf(av + __ldg(V1b + lane), 0.f) * __ldg(V2W + lane);
        #pragma unroll
        for (int d = 16; d; d >>= 1)
            v1 += __shfl_xor_sync(0xffffffffu, v1, d);
        epi_buf[(size_t)row * 65 + lane]      = b1v;
        epi_buf[(size_t)row * 65 + 32 + lane] = wfv;
        if (lane == 0)
            epi_buf[(size_t)row * 65 + 64] = v1 + __ldg(V2b);
    }
    __syncthreads();

    // ---- GAT per head, hp register-resident (lane = d, 32 dims) ----
    float* sat = sattn + w * 320;             // [16][20]
    const float* hsrow = shs + w * 1024;      // [16][64]

    for (int h = 0; h < 4; h++) {
        float hp[16];
        #pragma unroll
        for (int n = 0; n < 16; n++) hp[n] = 0.f;

        const float* Wcol = Wg + h * 32 + lane;
        #pragma unroll 4
        for (int kq = 0; kq < 16; kq++) {
            const float w0 = __ldg(Wcol + (4 * kq + 0) * 128);
            const float w1 = __ldg(Wcol + (4 * kq + 1) * 128);
            const float w2 = __ldg(Wcol + (4 * kq + 2) * 128);
            const float w3 = __ldg(Wcol + (4 * kq + 3) * 128);
            #pragma unroll
            for (int n = 0; n < 16; n++) {
                const float4 hv = *(const float4*)(hsrow + n * 64 + kq * 4);
                hp[n] += hv.x * w0 + hv.y * w1 + hv.z * w2 + hv.w * w3;
            }
        }

        // src/dst via butterfly reductions over d (=lanes)
        const float asrc = __ldg(att + h * 64 + lane);
        const float adst = __ldg(att + h * 64 + 32 + lane);
        float srcv[16], dstv[16];
        #pragma unroll
        for (int n = 0; n < 16; n++) {
            float ps = hp[n] * asrc, pd = hp[n] * adst;
            #pragma unroll
            for (int d = 16; d; d >>= 1) {
                ps += __shfl_xor_sync(0xffffffffu, ps, d);
                pd += __shfl_xor_sync(0xffffffffu, pd, d);
            }
            srcv[n] = ps; dstv[n] = pd;
        }

        // softmax: lane handles (i = lane&15, j in (lane>>4)*8 .. +8)
        {
            const int i  = lane & 15;
            const int jb = (lane >> 4) * 8;
            float e[8], mx = -1e30f;
            #pragma unroll
            for (int jj = 0; jj < 8; jj++) {
                float x = srcv[i] + dstv[jb + jj];
                x = x > 0.f ? x : 0.2f * x;      // leaky_relu 0.2
                e[jj] = x;
                mx = fmaxf(mx, x);
            }
            mx = fmaxf(mx, __shfl_xor_sync(0xffffffffu, mx, 16));
            float s = 0.f;
            #pragma unroll
            for (int jj = 0; jj < 8; jj++) { e[jj] = expf(e[jj] - mx); s += e[jj]; }
            s += __shfl_xor_sync(0xffffffffu, s, 16);
            const float inv = 1.f / s;
            #pragma unroll
            for (int jj = 0; jj < 8; jj++)
                sat[i * 20 + jb + jj] = e[jj] * inv;
        }
        __syncwarp();

        // g[i][d] = elu( sum_j attn[i][j] * hp[j][d] ), lane = d
        float* gbase = g_buf + (((size_t)(brow + w) * 4 + h) * 16) * 32 + lane;
        #pragma unroll 2
        for (int i = 0; i < 16; i++) {
            const float4 a0 = *(const float4*)(sat + i * 20);
            const float4 a1 = *(const float4*)(sat + i * 20 + 4);
            const float4 a2 = *(const float4*)(sat + i * 20 + 8);
            const float4 a3 = *(const float4*)(sat + i * 20 + 12);
            float gv = a0.x*hp[0] + a0.y*hp[1] + a0.z*hp[2] + a0.w*hp[3]
                     + a1.x*hp[4] + a1.y*hp[5] + a1.z*hp[6] + a1.w*hp[7]
                     + a2.x*hp[8] + a2.y*hp[9] + a2.z*hp[10]+ a2.w*hp[11]
                     + a3.x*hp[12]+ a3.y*hp[13]+ a3.z*hp[14]+ a3.w*hp[15];
            gv = gv > 0.f ? gv : expm1f(gv);     // elu
            gbase[i * 32] = gv;
        }
        __syncwarp();                            // sat reused next head
    }
}

// =========================== Kernel B: fused mixer v3 =======================
// 16 rows/block, 256 blocks, 512 threads, 2 CTAs/SM (32 warps/SM).
// smem floats: sT(2064) sqs(256) Wc(4 x 4 x 1024 = 16384) w1acc(256*33=8448)
//            = 27152 floats = 108608 B
#define SMEM_B_FLOATS (2064 + 256 + 16384 + 8448)

__device__ __forceinline__ void cp_async16(float* s, const float* g) {
    unsigned a = (unsigned)__cvta_generic_to_shared(s);
    asm volatile("cp.async.cg.shared.global [%0], [%1], 16;" :: "r"(a), "l"(g));
}

__global__ __launch_bounds__(512, 2)
void mix_kernel(const float* __restrict__ qs_g,
                const float* __restrict__ s_g,
                const float* __restrict__ unc_g,
                const float* __restrict__ w1sW,
                const float* __restrict__ w1sb,
                float* __restrict__ out)
{
    extern __shared__ float sm[];
    float* sT    = sm;               // [129][16]  s_aug transposed
    float* sqs   = sT + 2064;        // [16][16]
    float* Wc    = sqs + 256;        // ring: 4 x [4][1024]
    float* w1acc = Wc + 16384;       // [256][33]

    const int tid  = threadIdx.x;
    const int brow = blockIdx.x * 16;
    const int lane = tid & 31;

    // stage s (transposed), unc, qs; zero w1acc
    for (int idx = tid; idx < 2048; idx += 512) {
        int r = idx >> 7, k = idx & 127;
        sT[k * 16 + r] = s_g[(size_t)(brow + r) * 128 + k];
    }
    if (tid < 16) sT[128 * 16 + tid] = unc_g[brow + tid];
    if (tid < 256) {
        int r = tid >> 4, n = tid & 15;
        sqs[tid] = qs_g[(size_t)(brow + r) * 16 + n];
    }
    for (int idx = tid; idx < 8448; idx += 512) w1acc[idx] = 0.f;
    __syncthreads();

    const int colg = tid & 127;      // 128 column-groups
    const int rowg = tid >> 7;       // 4 row-groups of 4
    const int cA   = colg * 4;       // cols cA..+3 and 512+cA..+3
    const int r0   = rowg * 4;
    const int e0   = colg >> 3;
    const int d0   = (colg & 7) * 4;

    // precomputed cp.async slots for this thread (2 per chunk)
    const int kk0 = tid >> 8,           cc0 = (tid & 255) * 4;
    const int kk1 = (tid + 512) >> 8,   cc1 = ((tid + 512) & 255) * 4;

    for (int h = 0; h < 4; h++) {
        const float* Wh = w1sW + h * 1024;

        // prologue: issue chunks 0,1,2 (each = 4 k-rows x 1024 cols)
        #pragma unroll
        for (int c = 0; c < 3; c++) {
            float* dst = Wc + (c & 3) * 4096;
            const float* src = Wh + (size_t)c * 4 * 4096;
            cp_async16(dst + kk0 * 1024 + cc0, src + (size_t)kk0 * 4096 + cc0);
            cp_async16(dst + kk1 * 1024 + cc1, src + (size_t)kk1 * 4096 + cc1);
            asm volatile("cp.async.commit_group;");
        }

        float acc[4][8];
        #pragma unroll
        for (int i = 0; i < 4; i++)
            #pragma unroll
            for (int j = 0; j < 8; j++) acc[i][j] = 0.f;

        #pragma unroll 1
        for (int kb = 0; kb < 32; kb++) {
            if (kb < 30) asm volatile("cp.async.wait_group 2;");
            else         asm volatile("cp.async.wait_group 0;");
            __syncthreads();

            if (kb + 3 < 32) {
                float* dst = Wc + ((kb + 3) & 3) * 4096;
                const float* src = Wh + (size_t)(kb + 3) * 4 * 4096;
                cp_async16(dst + kk0 * 1024 + cc0, src + (size_t)kk0 * 4096 + cc0);
                cp_async16(dst + kk1 * 1024 + cc1, src + (size_t)kk1 * 4096 + cc1);
                asm volatile("cp.async.commit_group;");
            }

            const float* W = Wc + (kb & 3) * 4096;
            const float* sTk = sT + kb * 4 * 16;
            #pragma unroll
            for (int kk = 0; kk < 4; kk++) {
                const float4 sa = *(const float4*)(sTk + kk * 16 + r0);
                const float4 w0 = *(const float4*)(W + kk * 1024 + cA);
                const float4 w1 = *(const float4*)(W + kk * 1024 + 512 + cA);
                const float sr[4] = {sa.x, sa.y, sa.z, sa.w};
                #pragma unroll
                for (int i = 0; i < 4; i++) {
                    acc[i][0] += sr[i] * w0.x; acc[i][1] += sr[i] * w0.y;
                    acc[i][2] += sr[i] * w0.z; acc[i][3] += sr[i] * w0.w;
                    acc[i][4] += sr[i] * w1.x; acc[i][5] += sr[i] * w1.y;
                    acc[i][6] += sr[i] * w1.z; acc[i][7] += sr[i] * w1.w;
                }
            }
        }

        // tail: K row 128 (uncertainty) rank-1 + bias
        {
            const float4 w0 = __ldg((const float4*)(w1sW + (size_t)128 * 4096 + h * 1024 + cA));
            const float4 w1 = __ldg((const float4*)(w1sW + (size_t)128 * 4096 + h * 1024 + 512 + cA));
            const float4 b0 = __ldg((const float4*)(w1sb + h * 1024 + cA));
            const float4 b1 = __ldg((const float4*)(w1sb + h * 1024 + 512 + cA));
            #pragma unroll
            for (int i = 0; i < 4; i++) {
                const float su = sT[128 * 16 + r0 + i];
                acc[i][0] += su * w0.x + b0.x; acc[i][1] += su * w0.y + b0.y;
                acc[i][2] += su * w0.z + b0.z; acc[i][3] += su * w0.w + b0.w;
                acc[i][4] += su * w1.x + b1.x; acc[i][5] += su * w1.y + b1.y;
                acc[i][6] += su * w1.z + b1.z; acc[i][7] += su * w1.w + b1.w;
            }
        }

        // contraction: w1acc[r][n][e] += |sum_d ws[r][e*32+d] g[r][n][d]|
        // (register partials + 8-lane d-octet shfl reduce)
        for (int n = 0; n < 16; n++) {
            #pragma unroll
            for (int i = 0; i < 4; i++) {
                const float4 gv = __ldg((const float4*)(
                    g_buf + (((size_t)(brow + r0 + i) * 4 + h) * 16 + n) * 32 + d0));
                float p0 = acc[i][0]*gv.x + acc[i][1]*gv.y + acc[i][2]*gv.z + acc[i][3]*gv.w;
                float p1 = acc[i][4]*gv.x + acc[i][5]*gv.y + acc[i][6]*gv.z + acc[i][7]*gv.w;
                p0 += __shfl_xor_sync(0xffffffffu, p0, 1);
                p1 += __shfl_xor_sync(0xffffffffu, p1, 1);
                p0 += __shfl_xor_sync(0xffffffffu, p0, 2);
                p1 += __shfl_xor_sync(0xffffffffu, p1, 2);
                p0 += __shfl_xor_sync(0xffffffffu, p0, 4);
                p1 += __shfl_xor_sync(0xffffffffu, p1, 4);
                if ((lane & 7) == 0) {
                    float* wa = w1acc + ((r0 + i) * 16 + n) * 33;
                    wa[e0]      += fabsf(p0);
                    wa[e0 + 16] += fabsf(p1);
                }
            }
        }
        // no barrier needed: each thread RMWs only its own w1acc slots,
        // and the pipeline's iter-0 wait+sync orders buffer reuse.
    }
    __syncthreads();

    // ---- epilogue: warp = row (16 warps), lane = e (EMB=32) ----
    {
        const int r = tid >> 5, e = lane;
        float ha = 0.f;
        #pragma unroll
        for (int n = 0; n < 16; n++)
            ha += sqs[r * 16 + n] * w1acc[(r * 16 + n) * 33 + e];
        const size_t eb = (size_t)(brow + r) * 65;
        float hid = 0.25f * ha + epi_buf[eb + e];
        hid = hid > 0.f ? hid : expm1f(hid);      // elu
        float ys = hid * epi_buf[eb + 32 + e];
        #pragma unroll
        for (int d = 16; d; d >>= 1)
            ys += __shfl_xor_sync(0xffffffffu, ys, d);
        if (e == 0)
            out[brow + r] = ys + epi_buf[eb + 64];
    }
}

// =============================================================================
extern "C" void kernel_launch(void* const* d_in, const int* in_sizes, int n_in,
                              void* d_out, int out_size)
{
    const float* qs   = (const float*)d_in[0];
    const float* st   = (const float*)d_in[1];
    const float* hs   = (const float*)d_in[2];
    const float* unc  = (const float*)d_in[3];
    const float* Wg   = (const float*)d_in[4];
    const float* att  = (const float*)d_in[5];
    const float* w1sW = (const float*)d_in[6];
    const float* w1sb = (const float*)d_in[7];
    const float* b1W  = (const float*)d_in[8];
    const float* b1b  = (const float*)d_in[9];
    const float* wfW  = (const float*)d_in[10];
    const float* wfb  = (const float*)d_in[11];
    const float* V1W  = (const float*)d_in[12];
    const float* V1b  = (const float*)d_in[13];
    const float* V2W  = (const float*)d_in[14];
    const float* V2b  = (const float*)d_in[15];
    float* out = (float*)d_out;

    (void)in_sizes; (void)n_in; (void)out_size;

    cudaFuncSetAttribute(gat_kernel, cudaFuncAttributeMaxDynamicSharedMemorySize,
                         GAT_SMEM_FLOATS * sizeof(float));
    cudaFuncSetAttribute(mix_kernel, cudaFuncAttributeMaxDynamicSharedMemorySize,
                         SMEM_B_FLOATS * sizeof(float));

    gat_kernel<<<512, 256, GAT_SMEM_FLOATS * sizeof(float)>>>(
        hs, Wg, att, st, b1W, b1b, wfW, wfb, V1W, V1b, V2W, V2b);
    mix_kernel<<<256, 512, SMEM_B_FLOATS * sizeof(float)>>>(
        qs, st, unc, w1sW, w1sb, out);
}